// round 6
// baseline (speedup 1.0000x reference)
#include <cuda_runtime.h>
#include <cuda_bf16.h>
#include <cstdint>

#define N_ 128
#define C_ 81
#define A_ 8732
#define A4_ 2183          // A_/4 exactly

// Scratch (device globals — no allocations allowed)
__device__ unsigned g_con[N_ * A_];        // focal bits (dl==0 rows only), positives = 0u
__device__ float    g_partcon[N_ * 16];
__device__ int      g_partpos[N_ * 16];
__device__ float    g_row[N_];
__device__ unsigned g_done[N_];            // per-row producer completion (self-resetting)
__device__ unsigned g_count;               // consumer arrival count (self-resetting)

// ---------------------------------------------------------------------------
// One kernel, grid = N_*10, block = 256.
//   j = bid%10 < 9 : producer — focal loss for 1/9 of row n
//   j == 9         : consumer — smooth-L1, wait for row's producers, radix
//                    select top-k negatives, row loss; last consumer -> mean
// ---------------------------------------------------------------------------
__global__ __launch_bounds__(256, 8) void k_all(const float* __restrict__ ploc,
                                                const float* __restrict__ plabel,
                                                const float* __restrict__ gloc,
                                                const int*   __restrict__ glabel,
                                                const int*   __restrict__ domain_label,
                                                const float* __restrict__ dboxes,
                                                float* __restrict__ out)
{
    __shared__ unsigned s_hist[2048];    // 8 warp-private 256-bin histograms
    __shared__ unsigned s_hsum[256];
    __shared__ unsigned s_state[4];      // prefix, mask, kk, gt
    __shared__ float    s_redf[8];
    __shared__ int      s_redi[8];
    __shared__ float    s_sl1;
    __shared__ unsigned s_last;

    const int bid = blockIdx.x;
    const int n   = bid / 10;
    const int j   = bid - n * 10;
    const int tid = threadIdx.x;
    const int wid = tid >> 5, lane = tid & 31;

    if (j < 9) {
        // ================= producer: focal loss =================
        if (domain_label[n] != 0) return;      // row contributes exactly 0

        int idx = j * 256 + tid;
        bool valid = (idx < A4_);
        int ii = valid ? idx : (A4_ - 1);

        const float4* P = (const float4*)(plabel + (size_t)n * C_ * A_) + ii;
        int4 g = ((const int4*)(glabel + (size_t)n * A_))[ii];

        float4 s  = make_float4(0.f, 0.f, 0.f, 0.f);
        float4 xg = make_float4(0.f, 0.f, 0.f, 0.f);
#pragma unroll 3
        for (int c = 0; c < C_; c++) {
            float4 x = __ldcs(P);
            P += A4_;
            if (c == g.x) xg.x = x.x;
            if (c == g.y) xg.y = x.y;
            if (c == g.z) xg.z = x.z;
            if (c == g.w) xg.w = x.w;
            s.x += __expf(x.x); s.y += __expf(x.y);
            s.z += __expf(x.z); s.w += __expf(x.w);
        }

        float lp0 = xg.x - __logf(s.x), lp1 = xg.y - __logf(s.y);
        float lp2 = xg.z - __logf(s.z), lp3 = xg.w - __logf(s.w);
        float o0 = 1.f - __expf(lp0), o1 = 1.f - __expf(lp1);
        float o2 = 1.f - __expf(lp2), o3 = 1.f - __expf(lp3);
        float c0 = -0.25f * o0 * o0 * lp0;
        float c1 = -0.25f * o1 * o1 * lp1;
        float c2 = -0.25f * o2 * o2 * lp2;
        float c3 = -0.25f * o3 * o3 * lp3;

        bool m0 = g.x > 0, m1 = g.y > 0, m2 = g.z > 0, m3 = g.w > 0;

        uint4 cw;
        cw.x = m0 ? 0u : __float_as_uint(c0);
        cw.y = m1 ? 0u : __float_as_uint(c1);
        cw.z = m2 ? 0u : __float_as_uint(c2);
        cw.w = m3 ? 0u : __float_as_uint(c3);
        ((uint4*)g_con)[(size_t)n * A4_ + ii] = cw;
        __threadfence();                       // order this thread's g_con writes

        float contrib = 0.f;
        int pc = 0;
        if (valid) {
            if (m0) { contrib += c0; pc++; }
            if (m1) { contrib += c1; pc++; }
            if (m2) { contrib += c2; pc++; }
            if (m3) { contrib += c3; pc++; }
        }
        for (int o = 16; o > 0; o >>= 1) {
            contrib += __shfl_down_sync(0xffffffffu, contrib, o);
            pc      += __shfl_down_sync(0xffffffffu, pc, o);
        }
        if (lane == 0) { s_redf[wid] = contrib; s_redi[wid] = pc; }
        __syncthreads();
        if (tid == 0) {
            float t = 0.f; int tp = 0;
#pragma unroll
            for (int q = 0; q < 8; q++) { t += s_redf[q]; tp += s_redi[q]; }
            g_partcon[n * 16 + j] = t;
            g_partpos[n * 16 + j] = tp;
            __threadfence();                   // release
            atomicAdd(&g_done[n], 1u);
        }
        return;
    }

    // ================= consumer: per-row tail =================
    const int dl = domain_label[n];
    float rowval = 0.f;

    if (dl == 0) {
        // ---- masked smooth-L1 (independent of producers) ----
        const int* G = glabel + (size_t)n * A_;
        float sl1 = 0.f;
        for (int i = tid; i < A_; i += 256) {
            if (G[i] > 0) {
                float gx = gloc[((size_t)n * 4 + 0) * A_ + i];
                float gy = gloc[((size_t)n * 4 + 1) * A_ + i];
                float gw = gloc[((size_t)n * 4 + 2) * A_ + i];
                float gh = gloc[((size_t)n * 4 + 3) * A_ + i];
                float dx = dboxes[0 * A_ + i], dy = dboxes[1 * A_ + i];
                float dw = dboxes[2 * A_ + i], dh = dboxes[3 * A_ + i];
                float px = ploc[((size_t)n * 4 + 0) * A_ + i];
                float py = ploc[((size_t)n * 4 + 1) * A_ + i];
                float pw = ploc[((size_t)n * 4 + 2) * A_ + i];
                float ph = ploc[((size_t)n * 4 + 3) * A_ + i];

                float v0 = 10.f * (gx - dx) / dw;
                float v1 = 10.f * (gy - dy) / dh;
                float v2 = 5.f * __logf(gw / dw);
                float v3 = 5.f * __logf(gh / dh);
                float d0 = px - v0, d1 = py - v1, d2 = pw - v2, d3 = ph - v3;
                float ad;
                ad = fabsf(d0); sl1 += (ad < 1.f) ? 0.5f * d0 * d0 : ad - 0.5f;
                ad = fabsf(d1); sl1 += (ad < 1.f) ? 0.5f * d1 * d1 : ad - 0.5f;
                ad = fabsf(d2); sl1 += (ad < 1.f) ? 0.5f * d2 * d2 : ad - 0.5f;
                ad = fabsf(d3); sl1 += (ad < 1.f) ? 0.5f * d3 * d3 : ad - 0.5f;
            }
        }
        for (int o = 16; o > 0; o >>= 1) sl1 += __shfl_down_sync(0xffffffffu, sl1, o);
        if (lane == 0) s_redf[wid] = sl1;
        __syncthreads();
        if (tid == 0) {
            float t = 0.f;
#pragma unroll
            for (int q = 0; q < 8; q++) t += s_redf[q];
            s_sl1 = t;
        }

        // ---- wait for this row's 9 producers ----
        if (tid == 0) {
            while (atomicAdd(&g_done[n], 0u) < 9u) __nanosleep(64);
            g_done[n] = 0u;                    // reset for next graph replay
            __threadfence();                   // acquire
        }
        __syncthreads();

        if (tid == 0) {
            float ps = 0.f; int pp = 0;
#pragma unroll
            for (int q = 0; q < 9; q++) { ps += g_partcon[n * 16 + q]; pp += g_partpos[n * 16 + q]; }
            s_redf[0] = ps; s_redi[0] = pp;
            s_state[0] = 0u; s_state[1] = 0u; s_state[3] = 0u;
        }
        __syncthreads();

        int   pos = s_redi[0];
        float ps  = s_redf[0];

        if (pos > 0) {
            int k = 3 * pos; if (k > A_) k = A_;
            if (tid == 0) s_state[2] = (unsigned)k;

            const uint4* gc = (const uint4*)g_con + (size_t)n * A4_;
            unsigned hb = (unsigned)wid << 8;

            // ---- 4-pass exact radix select (k-th largest), con from L2 ----
#pragma unroll
            for (int shift = 24; shift >= 0; shift -= 8) {
#pragma unroll
                for (int q = 0; q < 8; q++) s_hist[q * 256 + tid] = 0u;
                __syncthreads();
                unsigned pref = s_state[0], msk = s_state[1];
                for (int grp = tid; grp < A4_; grp += 256) {
                    uint4 x = __ldcg(gc + grp);
                    if ((x.x & msk) == pref) atomicAdd(&s_hist[hb + ((x.x >> shift) & 255u)], 1u);
                    if ((x.y & msk) == pref) atomicAdd(&s_hist[hb + ((x.y >> shift) & 255u)], 1u);
                    if ((x.z & msk) == pref) atomicAdd(&s_hist[hb + ((x.z >> shift) & 255u)], 1u);
                    if ((x.w & msk) == pref) atomicAdd(&s_hist[hb + ((x.w >> shift) & 255u)], 1u);
                }
                __syncthreads();
                {
                    unsigned h = s_hist[tid];
#pragma unroll
                    for (int q = 1; q < 8; q++) h += s_hist[q * 256 + tid];
                    s_hsum[tid] = h;
                }
                __syncthreads();
                if (tid < 32) {
                    unsigned base = (unsigned)tid << 3;
                    unsigned lh[8], ls[8];
#pragma unroll
                    for (int q = 0; q < 8; q++) lh[q] = s_hsum[base + q];
                    unsigned run = 0;
#pragma unroll
                    for (int q = 7; q >= 0; q--) { run += lh[q]; ls[q] = run; }
                    unsigned incl = run;
#pragma unroll
                    for (int o = 1; o < 32; o <<= 1) {
                        unsigned v = __shfl_down_sync(0xffffffffu, incl, o);
                        if (tid + o < 32) incl += v;
                    }
                    unsigned exh = incl - run;
                    unsigned kk = s_state[2];
#pragma unroll
                    for (int q = 0; q < 8; q++) {
                        unsigned suf = exh + ls[q];
                        unsigned gtc = suf - lh[q];
                        if (gtc < kk && suf >= kk) {
                            s_state[0] |= (base + q) << shift;
                            s_state[1] |= 0xFFu << shift;
                            s_state[2] = kk - gtc;
                            s_state[3] += gtc;
                        }
                    }
                }
                __syncthreads();
            }

            unsigned T    = s_state[0];
            unsigned ties = s_state[2];        // k - count(> T)

            float sgt = 0.f;
            for (int grp = tid; grp < A4_; grp += 256) {
                uint4 x = __ldcg(gc + grp);
                if (x.x > T) sgt += __uint_as_float(x.x);
                if (x.y > T) sgt += __uint_as_float(x.y);
                if (x.z > T) sgt += __uint_as_float(x.z);
                if (x.w > T) sgt += __uint_as_float(x.w);
            }
            for (int o = 16; o > 0; o >>= 1) sgt += __shfl_down_sync(0xffffffffu, sgt, o);
            if (lane == 0) s_redf[wid] = sgt;
            __syncthreads();
            if (tid == 0) {
                float v = 0.f;
#pragma unroll
                for (int q = 0; q < 8; q++) v += s_redf[q];
                float topk = v + (float)ties * __uint_as_float(T);
                rowval = (ps + s_sl1 + topk) / (float)pos;
            }
        }
    }

    if (tid == 0) {
        g_row[n] = rowval;
        __threadfence();
        unsigned old = atomicAdd(&g_count, 1u);
        s_last = (old == N_ - 1u) ? 1u : 0u;
    }
    __syncthreads();

    // ---- last-arriving consumer computes the mean ----
    if (s_last) {
        __threadfence();
        float v = (tid < N_) ? g_row[tid] : 0.f;
        for (int o = 16; o > 0; o >>= 1) v += __shfl_down_sync(0xffffffffu, v, o);
        if (lane == 0) s_redf[wid] = v;
        __syncthreads();
        if (tid == 0) {
            float t = 0.f;
#pragma unroll
            for (int q = 0; q < 4; q++) t += s_redf[q];   // warps 0-3 held 128 rows
            out[0] = t / (float)N_;
            g_count = 0u;                      // reset for next graph replay
        }
    }
}

extern "C" void kernel_launch(void* const* d_in, const int* in_sizes, int n_in,
                              void* d_out, int out_size)
{
    const float* ploc         = (const float*)d_in[0];
    const float* plabel       = (const float*)d_in[1];
    const float* gloc         = (const float*)d_in[2];
    const int*   glabel       = (const int*)  d_in[3];
    const int*   domain_label = (const int*)  d_in[4];
    const float* dboxes       = (const float*)d_in[5];
    float* out = (float*)d_out;

    k_all<<<N_ * 10, 256>>>(ploc, plabel, gloc, glabel, domain_label, dboxes, out);
}